// round 7
// baseline (speedup 1.0000x reference)
#include <cuda_runtime.h>
#include <cuda_bf16.h>
#include <math.h>
#include <stdint.h>

#define NGv 12
#define Bv  8
#define Sv  1280
#define Cv  512

typedef __nv_bfloat16 bf16;

// ---------------- device scratch ----------------
__device__ bf16  g_xh [Bv*Sv*Cv], g_xl [Bv*Sv*Cv];
__device__ bf16  g_xth[Bv*Cv*Sv], g_xtl[Bv*Cv*Sv];
__device__ bf16  g_wth[NGv*Cv*Cv], g_wtl[NGv*Cv*Cv];
__device__ bf16  g_wph[NGv*Cv*Cv], g_wpl[NGv*Cv*Cv];
__device__ bf16  g_wgh[NGv*Cv*Cv], g_wgl[NGv*Cv*Cv];
__device__ bf16  g_thh[Bv*Sv*Cv], g_thl[Bv*Sv*Cv];
__device__ bf16  g_phh[Bv*Sv*Cv], g_phl[Bv*Sv*Cv];
__device__ float g_sim[Bv*Sv*Sv];
__device__ bf16  g_ath[Bv*Sv*Sv], g_atl[Bv*Sv*Sv];
__device__ bf16  g_tph[Bv*Sv*Cv], g_tpl[Bv*Sv*Cv];
__device__ float g_agg[Bv*Sv*Cv];
__device__ float g_cx[Bv*Sv], g_cy[Bv*Sv], g_rr[Bv*Sv];
__device__ double g_stats[Bv*2];
__device__ float g_mu[Bv], g_rstd[Bv];

// ---------------- helpers ----------------
__device__ __forceinline__ uint32_t sm2u(const void* p) {
    uint32_t a;
    asm("{ .reg .u64 t; cvta.to.shared.u64 t, %1; cvt.u32.u64 %0, t; }" : "=r"(a) : "l"(p));
    return a;
}
#define SWZ(o) ((o) ^ (((o) >> 3) & 0x70u))

__device__ __forceinline__ void bsplit(float x, bf16& h, bf16& l) {
    h = __float2bfloat16(x);
    l = __float2bfloat16(x - __bfloat162float(h));
}

__device__ __forceinline__ void cpasync16(uint32_t dst, const void* src) {
    asm volatile("cp.async.cg.shared.global [%0], [%1], 16;" :: "r"(dst), "l"(src));
}
// .noinc is load-bearing (R4 deadlock otherwise).
__device__ __forceinline__ void cpasync_arrive_noinc(uint32_t bar) {
    asm volatile("cp.async.mbarrier.arrive.noinc.shared.b64 [%0];" :: "r"(bar));
}
__device__ __forceinline__ void mbar_init(uint32_t bar, uint32_t cnt) {
    asm volatile("mbarrier.init.shared.b64 [%0], %1;" :: "r"(bar), "r"(cnt) : "memory");
}
__device__ __forceinline__ void mbar_wait(uint32_t bar, uint32_t parity) {
    asm volatile(
        "{\n\t"
        ".reg .pred P;\n\t"
        "WL%=:\n\t"
        "mbarrier.try_wait.parity.acquire.cta.shared::cta.b64 P, [%0], %1;\n\t"
        "@P bra WD%=;\n\t"
        "bra WL%=;\n\t"
        "WD%=:\n\t"
        "}"
        :: "r"(bar), "r"(parity) : "memory");
}
__device__ __forceinline__ void fence_proxy_async_g() {
    asm volatile("fence.proxy.async;" ::: "memory");
}
// arrive on rank0's mbarrier at the same SMEM offset
__device__ __forceinline__ void mbar_arrive_rank0(uint32_t localaddr) {
    asm volatile(
        "{\n\t"
        ".reg .b32 ra;\n\t"
        "mapa.shared::cluster.u32 ra, %0, %1;\n\t"
        "mbarrier.arrive.shared::cluster.b64 _, [ra];\n\t"
        "}"
        :: "r"(localaddr), "r"(0) : "memory");
}
#define CLUSTER_SYNC() do { \
    asm volatile("barrier.cluster.arrive.aligned;" ::: "memory"); \
    asm volatile("barrier.cluster.wait.aligned;" ::: "memory"); \
} while (0)

#if defined(__CUDA_ARCH_FEAT_SM103_ALL) || !defined(__CUDA_ARCH__)
#define HAS_TCGEN05 1
#else
#define HAS_TCGEN05 0
#endif

#if HAS_TCGEN05
__device__ __forceinline__ void tc_commit_mc2(uint32_t bar) {
    asm volatile(
        "tcgen05.commit.cta_group::2.mbarrier::arrive::one.shared::cluster.multicast::cluster.b64 [%0], %1;"
        :: "r"(bar), "h"((uint16_t)0x3) : "memory");
}
__device__ __forceinline__ void mma_bf16_cg2(uint32_t d, uint64_t ad, uint64_t bd, uint32_t idesc, bool acc) {
    uint32_t e = acc ? 1u : 0u;
    asm volatile(
        "{\n\t"
        ".reg .pred p;\n\t"
        "setp.ne.u32 p, %6, 0;\n\t"
        "tcgen05.mma.cta_group::2.kind::f16 [%0], %1, %2, %3, "
        "{%4, %4, %4, %4, %4, %4, %4, %4}, p;\n\t"
        "}"
        :: "r"(d), "l"(ad), "l"(bd), "r"(idesc), "r"(0u), "r"(0u), "r"(e) : "memory");
}
#define TC_ALLOC_CG2(smemaddr, n) \
    asm volatile("tcgen05.alloc.cta_group::2.sync.aligned.shared::cta.b32 [%0], %1;" \
                 :: "r"(smemaddr), "r"((uint32_t)(n)) : "memory")
#define TC_RELINQ_CG2() \
    asm volatile("tcgen05.relinquish_alloc_permit.cta_group::2.sync.aligned;")
#define TC_DEALLOC_CG2(tm, n) \
    asm volatile("tcgen05.dealloc.cta_group::2.sync.aligned.b32 %0, %1;" :: "r"(tm), "r"((uint32_t)(n)))
#define TC_FENCE_AFTER()  asm volatile("tcgen05.fence::after_thread_sync;" ::: "memory")
#define TC_WAIT_LD()      asm volatile("tcgen05.wait::ld.sync.aligned;" ::: "memory")
#define LDTM32(r, a) \
    asm volatile( \
        "tcgen05.ld.sync.aligned.32x32b.x32.b32 " \
        "{%0, %1, %2, %3, %4, %5, %6, %7, " \
        " %8, %9, %10, %11, %12, %13, %14, %15, " \
        " %16, %17, %18, %19, %20, %21, %22, %23, " \
        " %24, %25, %26, %27, %28, %29, %30, %31}, [%32];" \
        : "=r"((r)[0]),  "=r"((r)[1]),  "=r"((r)[2]),  "=r"((r)[3]), \
          "=r"((r)[4]),  "=r"((r)[5]),  "=r"((r)[6]),  "=r"((r)[7]), \
          "=r"((r)[8]),  "=r"((r)[9]),  "=r"((r)[10]), "=r"((r)[11]), \
          "=r"((r)[12]), "=r"((r)[13]), "=r"((r)[14]), "=r"((r)[15]), \
          "=r"((r)[16]), "=r"((r)[17]), "=r"((r)[18]), "=r"((r)[19]), \
          "=r"((r)[20]), "=r"((r)[21]), "=r"((r)[22]), "=r"((r)[23]), \
          "=r"((r)[24]), "=r"((r)[25]), "=r"((r)[26]), "=r"((r)[27]), \
          "=r"((r)[28]), "=r"((r)[29]), "=r"((r)[30]), "=r"((r)[31]) \
        : "r"(a))
#endif

static constexpr uint64_t DESC_BASE =
    (2ull << 61) | (1ull << 46) | (64ull << 32) | (1ull << 16);   // SW128, Blackwell, SBO=64, LBO=1
__device__ __forceinline__ uint64_t mk_desc(uint32_t addr) {
    return DESC_BASE | ((uint64_t)(addr >> 4) & 0x3FFFull);
}

// idesc cg2 kind::f16: dtype=F32(1<<4), atype=BF16(1<<7), btype=BF16(1<<10),
// N=256 (32<<17), M_total=256 (16<<24)
static constexpr uint32_t IDESC_CG2 = (1u << 4) | (1u << 7) | (1u << 10) | (32u << 17) | (16u << 24);

// -------- tcgen05 cg2 3xBF16 GEMM: D = alpha*(A @ B^T) + bias, tile 256x256 --------
// Cluster (2,1,1): rank r holds A rows [m0+r*128, +128) and B rows [col0+r*128, +128).
// Per-CTA stage 64KB (Ah 16K | Al 16K | Bh 16K | Bl 16K), KC=64, 3 stages.
#define KC 64
#define STG_BYTES 65536
#define OFF_AL 16384
#define OFF_BH 32768
#define OFF_BL 49152
#define NSTG 3
#define DYN_BYTES (NSTG * STG_BYTES)

__global__ __launch_bounds__(160, 1) __cluster_dims__(2, 1, 1)
void tcgemm(const bf16* __restrict__ Ah, const bf16* __restrict__ Al, size_t sAz, int ldA,
            const bf16* __restrict__ Bh, const bf16* __restrict__ Bl,
            const bf16* __restrict__ Bh2, const bf16* __restrict__ Bl2, size_t sBz, int ldB,
            float* outF, bf16* outH, bf16* outL, bf16* outH2, bf16* outL2,
            size_t sOz, int ldO,
            const float* bias, const float* bias2, float alpha, int K, int zsplit)
{
    const int rank = blockIdx.x & 1;
    const int col0 = (blockIdx.x >> 1) * 256;
    const int m0   = blockIdx.y * 256;
    int z = blockIdx.z;
    if (z >= zsplit) { z -= zsplit; Bh = Bh2; Bl = Bl2; outH = outH2; outL = outL2; bias = bias2; }

#if HAS_TCGEN05
    extern __shared__ __align__(1024) char dynsm[];
    __shared__ __align__(8) uint64_t s_full[NSTG], s_empty[NSTG], s_done;
    __shared__ uint32_t s_tptr;

    const int tid = threadIdx.x;
    const int wid = tid >> 5;
    const int lane = tid & 31;

    const uint32_t dynu = sm2u(dynsm);
    uint32_t fullb[NSTG], emptyb[NSTG];
    #pragma unroll
    for (int s = 0; s < NSTG; s++) { fullb[s] = sm2u(&s_full[s]); emptyb[s] = sm2u(&s_empty[s]); }
    const uint32_t doneb = sm2u(&s_done);

    if (tid == 0) {
        // rank0 full barrier also receives the relay arrive from rank1
        #pragma unroll
        for (int s = 0; s < NSTG; s++) {
            mbar_init(fullb[s], rank == 0 ? 129 : 128);
            mbar_init(emptyb[s], 1);
        }
        mbar_init(doneb, 1);
    }
    __syncthreads();
    if (wid == 4) {
        TC_ALLOC_CG2(sm2u(&s_tptr), 256);
        TC_RELINQ_CG2();
    }
    __syncthreads();
    const uint32_t tmem = s_tptr;

    // barriers + TMEM alloc visible cluster-wide before any remote arrive / peer read
    CLUSTER_SYNC();

    const int nk = K / KC;

    if (wid < 4) {
        // ---- producers (128 threads): this CTA's A half + B half ----
        const bf16* aH = Ah + (size_t)z * sAz + (size_t)(m0 + rank * 128) * ldA;
        const bf16* aL = Al + (size_t)z * sAz + (size_t)(m0 + rank * 128) * ldA;
        const bf16* bH = Bh + (size_t)z * sBz + (size_t)(col0 + rank * 128) * ldB;
        const bf16* bL = Bl + (size_t)z * sBz + (size_t)(col0 + rank * 128) * ldB;
        int st = 0, ph = 1;
        for (int c = 0; c < nk; c++) {
            mbar_wait(emptyb[st], ph);
            const uint32_t sb = dynu + st * STG_BYTES;
            const int k0 = c * KC;
            #pragma unroll
            for (int i = 0; i < 8; i++) {
                int idx = i * 128 + tid;
                int r = idx >> 3, cc = idx & 7;
                uint32_t so = SWZ((uint32_t)(r * 128 + cc * 16));
                const size_t goA = (size_t)r * ldA + k0 + cc * 8;
                const size_t goB = (size_t)r * ldB + k0 + cc * 8;
                cpasync16(sb + so, aH + goA);
                cpasync16(sb + OFF_AL + so, aL + goA);
                cpasync16(sb + OFF_BH + so, bH + goB);
                cpasync16(sb + OFF_BL + so, bL + goB);
            }
            cpasync_arrive_noinc(fullb[st]);
            if (++st == NSTG) { st = 0; ph ^= 1; }
        }
    } else if (lane == 0) {
        if (rank == 0) {
            // ---- MMA issuer (leader) ----
            int st = 0, ph = 0;
            for (int c = 0; c < nk; c++) {
                mbar_wait(fullb[st], ph);
                fence_proxy_async_g();
                const uint32_t sb = dynu + st * STG_BYTES;
                uint64_t dah = mk_desc(sb),          dal = mk_desc(sb + OFF_AL);
                uint64_t dbh = mk_desc(sb + OFF_BH), dbl = mk_desc(sb + OFF_BL);
                #pragma unroll
                for (int ks = 0; ks < 4; ks++)
                    mma_bf16_cg2(tmem, dah + ks * 2, dbh + ks * 2, IDESC_CG2, !(c == 0 && ks == 0));
                #pragma unroll
                for (int ks = 0; ks < 4; ks++)
                    mma_bf16_cg2(tmem, dah + ks * 2, dbl + ks * 2, IDESC_CG2, true);
                #pragma unroll
                for (int ks = 0; ks < 4; ks++)
                    mma_bf16_cg2(tmem, dal + ks * 2, dbh + ks * 2, IDESC_CG2, true);
                tc_commit_mc2(emptyb[st]);
                if (++st == NSTG) { st = 0; ph ^= 1; }
            }
            tc_commit_mc2(doneb);
        } else {
            // ---- relay (rank1): local data ready -> arrive on leader's full ----
            int st = 0, ph = 0;
            for (int c = 0; c < nk; c++) {
                mbar_wait(fullb[st], ph);
                fence_proxy_async_g();   // make this CTA's cp.async data visible to async proxy
                mbar_arrive_rank0(fullb[st]);
                if (++st == NSTG) { st = 0; ph ^= 1; }
            }
        }
    }

    // ---- epilogue: every CTA reads its own TMEM half (its 128 M-rows) ----
    mbar_wait(doneb, 0);
    TC_FENCE_AFTER();

    if (wid < 4) {
        float* tile = (float*)(dynsm + wid * 4352);     // 32x33 floats per warp
        const size_t obase = (size_t)z * sOz;
        const int mrow0 = m0 + rank * 128 + wid * 32;
        for (int c0 = 0; c0 < 256; c0 += 32) {
            uint32_t regs[32];
            LDTM32(regs, tmem + c0);
            TC_WAIT_LD();
            #pragma unroll
            for (int j = 0; j < 32; j++) {
                float v = __uint_as_float(regs[j]) * alpha;
                if (bias) v += bias[col0 + c0 + j];
                tile[lane * 33 + j] = v;
            }
            __syncwarp();
            #pragma unroll
            for (int i = 0; i < 8; i++) {
                int f = i * 32 + lane;
                int rr = f >> 3, q = (f & 7) * 4;
                float vv[4];
                vv[0] = tile[rr * 33 + q + 0];
                vv[1] = tile[rr * 33 + q + 1];
                vv[2] = tile[rr * 33 + q + 2];
                vv[3] = tile[rr * 33 + q + 3];
                size_t off = obase + (size_t)(mrow0 + rr) * ldO + col0 + c0 + q;
                if (outF) {
                    float4 o4 = { vv[0], vv[1], vv[2], vv[3] };
                    *(float4*)(outF + off) = o4;
                }
                if (outH) {
                    uint32_t hw[4], lw[4];
                    #pragma unroll
                    for (int t = 0; t < 4; t++) {
                        bf16 h, l;
                        bsplit(vv[t], h, l);
                        hw[t] = (uint32_t)__bfloat16_as_ushort(h);
                        lw[t] = (uint32_t)__bfloat16_as_ushort(l);
                    }
                    uint2 uh = { hw[0] | (hw[1] << 16), hw[2] | (hw[3] << 16) };
                    uint2 ul = { lw[0] | (lw[1] << 16), lw[2] | (lw[3] << 16) };
                    *(uint2*)(outH + off) = uh;
                    *(uint2*)(outL + off) = ul;
                }
            }
            __syncwarp();
        }
    }
    __syncthreads();
    if (wid == 4) TC_DEALLOC_CG2(tmem, 256);
    CLUSTER_SYNC();
#else
    // -------- plain-sm_103 fallback (insurance; never the selected cubin) --------
    const bf16* aH = Ah + (size_t)z * sAz;
    const bf16* aL = Al + (size_t)z * sAz;
    const bf16* bH = Bh + (size_t)z * sBz;
    const bf16* bL = Bl + (size_t)z * sBz;
    for (int idx = threadIdx.x; idx < 128 * 256; idx += blockDim.x) {
        int mi = m0 + rank * 128 + (idx >> 8);
        int ni = col0 + (idx & 255);
        const bf16* pa  = aH + (size_t)mi * ldA;
        const bf16* pa2 = aL + (size_t)mi * ldA;
        const bf16* pb  = bH + (size_t)ni * ldB;
        const bf16* pb2 = bL + (size_t)ni * ldB;
        float s = 0.f;
        for (int k = 0; k < K; k++)
            s += (__bfloat162float(pa[k]) + __bfloat162float(pa2[k])) *
                 (__bfloat162float(pb[k]) + __bfloat162float(pb2[k]));
        float v = s * alpha + (bias ? bias[ni] : 0.f);
        size_t off = (size_t)z * sOz + (size_t)mi * ldO + ni;
        if (outF) outF[off] = v;
        if (outH) {
            bf16 h, l;
            bsplit(v, h, l);
            outH[off] = h;
            outL[off] = l;
        }
    }
#endif
}

// ---------------- transpose + bf16 hi/lo split ----------------
__global__ void conv_t_kernel(const float* __restrict__ in, bf16* __restrict__ th,
                              bf16* __restrict__ tl, bf16* sh, bf16* sl, int R, int Cc)
{
    __shared__ float t[32][33];
    const int z = blockIdx.z;
    const size_t zb = (size_t)z * R * Cc;
    const int r0 = blockIdx.y * 32, c0 = blockIdx.x * 32;
    #pragma unroll
    for (int k = 0; k < 4; k++) {
        int r = r0 + threadIdx.y + k * 8;
        size_t idx = zb + (size_t)r * Cc + c0 + threadIdx.x;
        float v = in[idx];
        t[threadIdx.y + k * 8][threadIdx.x] = v;
        if (sh) {
            bf16 h, l;
            bsplit(v, h, l);
            sh[idx] = h;
            sl[idx] = l;
        }
    }
    __syncthreads();
    #pragma unroll
    for (int k = 0; k < 4; k++) {
        int cc = c0 + threadIdx.y + k * 8;
        int rr = r0 + threadIdx.x;
        float v = t[threadIdx.x][threadIdx.y + k * 8];
        size_t o = zb + (size_t)cc * R + rr;
        bf16 h, l;
        bsplit(v, h, l);
        th[o] = h;
        tl[o] = l;
    }
}

// ---------------- box centers ----------------
__global__ void pos_kernel(const float* __restrict__ box)
{
    int idx = blockIdx.x * blockDim.x + threadIdx.x;
    if (idx >= Bv * Sv) return;
    float cx = (box[idx * 4 + 0] + box[idx * 4 + 2]) * 0.5f;
    float cy = (box[idx * 4 + 1] + box[idx * 4 + 3]) * 0.5f;
    g_cx[idx] = cx; g_cy[idx] = cy; g_rr[idx] = cx * cx + cy * cy;
}

// ---------------- masked softmax -> bf16 hi/lo (+optional fp32 relation_graph) --------
__global__ __launch_bounds__(256)
void masked_softmax_kernel(const float* __restrict__ sim, bf16* __restrict__ aH,
                           bf16* __restrict__ aL, float* relF, const void* __restrict__ owp)
{
    const int row = blockIdx.x;
    const int b = row / Sv;
    const int tid = threadIdx.x;
    const float* srow = sim + (size_t)row * Sv;

    float ow = 224.0f;
    if (owp) {
        int vi = *(const int*)owp;
        ow = (vi > 0 && vi < 1000000) ? (float)vi : __int_as_float(vi);
    }
    const float thr2 = (0.2f * ow) * (0.2f * ow);

    const float rn = g_rr[row], cxn = g_cx[row], cyn = g_cy[row];
    const float* cxb = g_cx + b * Sv;
    const float* cyb = g_cy + b * Sv;
    const float* rb  = g_rr + b * Sv;

    float v[5];
    float mx = -INFINITY;
    #pragma unroll
    for (int u = 0; u < 5; u++) {
        int m = tid + u * 256;
        float d2 = (rn - 2.0f * (cxn * cxb[m] + cyn * cyb[m])) + rb[m];
        v[u] = (d2 > thr2) ? -INFINITY : srow[m];
        mx = fmaxf(mx, v[u]);
    }

    __shared__ float sh[8];
    #pragma unroll
    for (int o = 16; o > 0; o >>= 1) mx = fmaxf(mx, __shfl_xor_sync(0xffffffffu, mx, o));
    if ((tid & 31) == 0) sh[tid >> 5] = mx;
    __syncthreads();
    if (tid < 32) {
        float t = (tid < 8) ? sh[tid] : -INFINITY;
        #pragma unroll
        for (int o = 4; o > 0; o >>= 1) t = fmaxf(t, __shfl_xor_sync(0xffffffffu, t, o));
        if (tid == 0) sh[0] = t;
    }
    __syncthreads();
    mx = sh[0];
    __syncthreads();

    float sum = 0.f;
    #pragma unroll
    for (int u = 0; u < 5; u++) { v[u] = __expf(v[u] - mx); sum += v[u]; }
    #pragma unroll
    for (int o = 16; o > 0; o >>= 1) sum += __shfl_xor_sync(0xffffffffu, sum, o);
    if ((tid & 31) == 0) sh[tid >> 5] = sum;
    __syncthreads();
    if (tid < 32) {
        float t = (tid < 8) ? sh[tid] : 0.f;
        #pragma unroll
        for (int o = 4; o > 0; o >>= 1) t += __shfl_xor_sync(0xffffffffu, t, o);
        if (tid == 0) sh[0] = t;
    }
    __syncthreads();
    const float inv = 1.0f / sh[0];
    #pragma unroll
    for (int u = 0; u < 5; u++) {
        size_t o = (size_t)row * Sv + tid + u * 256;
        float p = v[u] * inv;
        bf16 h, l;
        bsplit(p, h, l);
        aH[o] = h;
        aL[o] = l;
        if (relF) relF[o] = p;
    }
}

// ---------------- LayerNorm statistics + finalize ----------------
__global__ void zero_stats_kernel()
{
    int i = threadIdx.x;
    if (i < Bv * 2) g_stats[i] = 0.0;
}

__global__ __launch_bounds__(256)
void reduce_stats_kernel(const float* __restrict__ agg)
{
    const int b = blockIdx.y;
    const float* p = agg + (size_t)b * Sv * Cv;
    double s = 0.0, q = 0.0;
    for (int i = blockIdx.x * blockDim.x + threadIdx.x; i < Sv * Cv; i += gridDim.x * blockDim.x) {
        float v = p[i];
        s += (double)v;
        q += (double)v * (double)v;
    }
    #pragma unroll
    for (int o = 16; o > 0; o >>= 1) {
        s += __shfl_xor_sync(0xffffffffu, s, o);
        q += __shfl_xor_sync(0xffffffffu, q, o);
    }
    __shared__ double shs[8], shq[8];
    const int tid = threadIdx.x;
    if ((tid & 31) == 0) { shs[tid >> 5] = s; shq[tid >> 5] = q; }
    __syncthreads();
    if (tid == 0) {
        for (int w = 1; w < 8; w++) { s += shs[w]; q += shq[w]; }
        atomicAdd(&g_stats[b * 2 + 0], s);
        atomicAdd(&g_stats[b * 2 + 1], q);
    }
}

__global__ void mustd_kernel()
{
    int b = threadIdx.x;
    if (b < Bv) {
        const double n = (double)Sv * (double)Cv;
        double mu = g_stats[b * 2 + 0] / n;
        double var = g_stats[b * 2 + 1] / n - mu * mu;
        g_mu[b] = (float)mu;
        g_rstd[b] = rsqrtf((float)var + 1e-5f);
    }
}

__global__ __launch_bounds__(256)
void finalize_kernel(const float* __restrict__ agg, const float* __restrict__ lns,
                     const float* __restrict__ lnb, float* __restrict__ out, int accumulate)
{
    size_t idx = (size_t)blockIdx.x * blockDim.x + threadIdx.x;
    if (idx >= (size_t)Bv * Sv * Cv) return;
    int b = (int)(idx / ((size_t)Sv * Cv));
    int j = (int)(idx % ((size_t)Sv * Cv));
    float v = (agg[idx] - g_mu[b]) * g_rstd[b] * lns[j] + lnb[j];
    v = fmaxf(v, 0.f);
    out[idx] = accumulate ? out[idx] + v : v;
}

// ---------------- launch ----------------
extern "C" void kernel_launch(void* const* d_in, const int* in_sizes, int n_in,
                              void* d_out, int out_size)
{
    const float* x   = (const float*)d_in[0];
    const float* box = (const float*)d_in[1];
    const float* Wt  = (const float*)d_in[2];
    const float* bt  = (const float*)d_in[3];
    const float* Wp  = (const float*)d_in[4];
    const float* bp  = (const float*)d_in[5];
    const float* Wg  = (const float*)d_in[6];
    const float* lns = (const float*)d_in[7];
    const float* lnb = (const float*)d_in[8];
    const void*  owp = (n_in > 10) ? d_in[10] : nullptr;

    float* out = (float*)d_out;
    float* rel = out + (size_t)Bv * Sv * Cv;

    bf16 *xh, *xl, *xth, *xtl, *wth, *wtl, *wph, *wpl, *wgh, *wgl;
    bf16 *thh, *thl, *phh, *phl, *ath, *atl, *tph, *tpl;
    float *sim, *agg;
    cudaGetSymbolAddress((void**)&xh,  g_xh);  cudaGetSymbolAddress((void**)&xl,  g_xl);
    cudaGetSymbolAddress((void**)&xth, g_xth); cudaGetSymbolAddress((void**)&xtl, g_xtl);
    cudaGetSymbolAddress((void**)&wth, g_wth); cudaGetSymbolAddress((void**)&wtl, g_wtl);
    cudaGetSymbolAddress((void**)&wph, g_wph); cudaGetSymbolAddress((void**)&wpl, g_wpl);
    cudaGetSymbolAddress((void**)&wgh, g_wgh); cudaGetSymbolAddress((void**)&wgl, g_wgl);
    cudaGetSymbolAddress((void**)&thh, g_thh); cudaGetSymbolAddress((void**)&thl, g_thl);
    cudaGetSymbolAddress((void**)&phh, g_phh); cudaGetSymbolAddress((void**)&phl, g_phl);
    cudaGetSymbolAddress((void**)&sim, g_sim);
    cudaGetSymbolAddress((void**)&ath, g_ath); cudaGetSymbolAddress((void**)&atl, g_atl);
    cudaGetSymbolAddress((void**)&tph, g_tph); cudaGetSymbolAddress((void**)&tpl, g_tpl);
    cudaGetSymbolAddress((void**)&agg, g_agg);

    cudaFuncSetAttribute(tcgemm, cudaFuncAttributeMaxDynamicSharedMemorySize, DYN_BYTES);

    const size_t sSC = (size_t)Sv * Cv;
    const size_t sSS = (size_t)Sv * Sv;
    const size_t sCC = (size_t)Cv * Cv;
    const float inv_sqrt = 0.04419417382415922f;
    const int NOSPLIT = 1 << 30;

    pos_kernel<<<(Bv * Sv + 255) / 256, 256>>>(box);
    conv_t_kernel<<<dim3(Cv / 32, Sv / 32, Bv), dim3(32, 8)>>>(x, xth, xtl, xh, xl, Sv, Cv);
    conv_t_kernel<<<dim3(Cv / 32, Cv / 32, NGv), dim3(32, 8)>>>(Wt, wth, wtl, nullptr, nullptr, Cv, Cv);
    conv_t_kernel<<<dim3(Cv / 32, Cv / 32, NGv), dim3(32, 8)>>>(Wp, wph, wpl, nullptr, nullptr, Cv, Cv);
    conv_t_kernel<<<dim3(Cv / 32, Cv / 32, NGv), dim3(32, 8)>>>(Wg, wgh, wgl, nullptr, nullptr, Cv, Cv);

    // grids: x = 2 * nNtiles (cluster pairs), y = nMtiles(256), z = batch (x2 for merged)
    for (int i = 0; i < NGv; i++) {
        // theta & phi merged: z<8 -> theta, z>=8 -> phi. N=512 -> 2 n-tiles.
        tcgemm<<<dim3(4, 5, 16), 160, DYN_BYTES>>>(
            xh, xl, sSC, Cv,
            wth + i * sCC, wtl + i * sCC, wph + i * sCC, wpl + i * sCC, 0, Cv,
            nullptr, thh, thl, phh, phl, sSC, Cv,
            bt + (size_t)i * Cv, bp + (size_t)i * Cv, 1.0f, Cv, 8);

        // sim = theta @ phi^T * inv_sqrt. N=1280 -> 5 n-tiles.
        tcgemm<<<dim3(10, 5, 8), 160, DYN_BYTES>>>(
            thh, thl, sSC, Cv,
            phh, phl, nullptr, nullptr, sSC, Cv,
            sim, nullptr, nullptr, nullptr, nullptr, sSS, Sv,
            nullptr, nullptr, inv_sqrt, Cv, NOSPLIT);

        masked_softmax_kernel<<<Bv * Sv, 256>>>(sim, ath, atl, (i == NGv - 1) ? rel : nullptr, owp);

        // tmp = attn @ x. N=512 -> 2 n-tiles, K=1280.
        tcgemm<<<dim3(4, 5, 8), 160, DYN_BYTES>>>(
            ath, atl, sSS, Sv,
            xth, xtl, nullptr, nullptr, (size_t)Cv * Sv, Sv,
            nullptr, tph, tpl, nullptr, nullptr, sSC, Cv,
            nullptr, nullptr, 1.0f, Sv, NOSPLIT);

        // agg = tmp @ W_gcn. N=512 -> 2 n-tiles.
        tcgemm<<<dim3(4, 5, 8), 160, DYN_BYTES>>>(
            tph, tpl, sSC, Cv,
            wgh + i * sCC, wgl + i * sCC, nullptr, nullptr, 0, Cv,
            agg, nullptr, nullptr, nullptr, nullptr, sSC, Cv,
            nullptr, nullptr, 1.0f, Cv, NOSPLIT);

        zero_stats_kernel<<<1, 32>>>();
        reduce_stats_kernel<<<dim3(64, Bv), 256>>>(agg);
        mustd_kernel<<<1, 32>>>();
        finalize_kernel<<<(int)((sSC * Bv + 255) / 256), 256>>>(
            agg, lns + (size_t)i * sSC, lnb + (size_t)i * sSC, out, i == 0 ? 0 : 1);
    }
}